// round 12
// baseline (speedup 1.0000x reference)
#include <cuda_runtime.h>
#include <cstdint>

// Problem constants
#define Bn 8
#define Tn 256
#define Un 64
#define Hn 512
#define Fn 1024

// Device scratch (no cudaMalloc allowed)
__device__ float g_act[(Bn * Tn + Bn * Un) * Hn];  // tf32-rounded inputs, 5 MB
__device__ float g_w[2 * Hn * Fn];                 // tf32-rounded W, 4 MB
__device__ float g_a[Bn * Tn * Fn];                // audio projection + bias, 8 MB
__device__ float g_l[Bn * Un * Fn];                // label projection, 2 MB
__device__ unsigned g_cnt[32];                     // readiness flags (b, tblock64)

__device__ __forceinline__ float to_tf32(float x) {
    float r;
    asm("cvt.rna.tf32.f32 %0, %1;" : "=f"(r) : "f"(x));
    return r;
}

// ---------------------------------------------------------------------------
// Prep: round GEMM operands to tf32 (RNA) once; block 0 zeroes the flags.
// ---------------------------------------------------------------------------
__global__ __launch_bounds__(256)
void prep_kernel(const float* __restrict__ audio,
                 const float* __restrict__ label,
                 const float* __restrict__ W)
{
    if (blockIdx.x == 0 && threadIdx.x < 32) g_cnt[threadIdx.x] = 0;

    const int NA = Bn * Tn * Hn / 4;   // 262144 float4
    const int NL = Bn * Un * Hn / 4;   // 65536
    int i = blockIdx.x * 256 + threadIdx.x;
    const float4* src;
    float4* dst;
    if (i < NA)           { src = (const float4*)audio + i;         dst = (float4*)g_act + i; }
    else if (i < NA + NL) { src = (const float4*)label + (i - NA);  dst = (float4*)g_act + i; }
    else                  { src = (const float4*)W + (i - NA - NL); dst = (float4*)g_w + (i - NA - NL); }
    float4 v = *src;
    float4 o = { to_tf32(v.x), to_tf32(v.y), to_tf32(v.z), to_tf32(v.w) };
    *dst = o;
}

// ---------------------------------------------------------------------------
// Main kernel: 2176 CTAs, 256 threads, <=64 regs, 38912 B dynamic smem (4/SM).
//
// bid < 128: GEMM producer. Each does 4 tiles (tile = bid + 128k, b ascending):
//   tile (b, tb in 4 [64 t], fb in 16 [64 f]); M=128 (64 audio t + 64 label u),
//   N=64, K=512, BK=16, warp tile 32x32, tf32 m16n8k8, 2-stage cp.async.
//   Epilogue writes g_a (+bias) / g_l, then threadfence + atomicAdd(flag).
//   Label tiles written redundantly by the 4 tb-CTAs (identical values).
//
// bid >= 128: bcast consumer (round-3 proven kernel + flag wait).
//   tile (b, tb8 in 32 [8 t], fb in 8 [128 f]); waits g_cnt[b*4+tb8/8]==16,
//   stages a (4KB) + l (32KB) in smem, streams 256 KB with .cs stores.
//   b-major bid order so wave-1 consumers match the earliest producer tiles.
// ---------------------------------------------------------------------------
#define STG_FL 4864              // gemm stage floats (AL 128x20 + Wa 16x72 + Wl)
#define SMEM_BYTES 38912
#define NGEMM 128

extern __shared__ float smem[];

#define CPA16(dst, src) \
    asm volatile("cp.async.cg.shared.global [%0], [%1], 16;" :: "r"(dst), "l"(src))

__global__ __launch_bounds__(256, 4)
void joint_main(const float* __restrict__ bias, float* __restrict__ out)
{
    const int tid  = threadIdx.x;
    const int bid  = blockIdx.x;

    if (bid < NGEMM) {
        // ========================= GEMM producer =========================
        const int warp = tid >> 5;
        const int lane = tid & 31;
        const int role = warp >> 2;           // 0 = audio, 1 = label
        const int w4   = warp & 3;
        const int wm   = w4 >> 1;             // 0..1 (M)
        const int wn_  = w4 & 1;              // 0..1 (N)
        const int g    = lane >> 2;           // 0..7
        const int tig  = lane & 3;            // 0..3

        const uint32_t sb = (uint32_t)__cvta_generic_to_shared(smem);

        // cp.async per-thread coordinates (BK=16)
        const int rA = tid >> 2;              // 0..63
        const int cA = tid & 3;               // float4 along K
        const uint32_t dA = (uint32_t)(rA * 20 + cA * 4) * 4;
        const uint32_t dL = dA + 5120u;       // +64 rows * 20 floats (bytes)
        const int kr = tid >> 4;              // 0..15
        const int cw = tid & 15;              // float4 along N(64)
        const uint32_t dWa = (uint32_t)(2560 + kr * 72 + cw * 4) * 4;
        const uint32_t dWl = dWa + 1152u * 4;
        const int WOFF = Hn * Fn;

#pragma unroll 1
        for (int k = 0; k < 4; ++k) {
            const int tile = bid + NGEMM * k;     // 0..511, b ascending
            const int b  = tile >> 6;
            const int tb = (tile >> 4) & 3;
            const int fb = tile & 15;

            const float* a_src = g_act + (size_t)(b * Tn + tb * 64 + rA) * Hn + cA * 4;
            const float* l_src = g_act + (size_t)(Bn * Tn + b * Un + rA) * Hn + cA * 4;
            const float* w_src = g_w + (size_t)kr * Fn + fb * 64 + cw * 4;

            float c[2][4][4];
#pragma unroll
            for (int mt = 0; mt < 2; mt++)
#pragma unroll
                for (int nt = 0; nt < 4; nt++)
#pragma unroll
                    for (int r = 0; r < 4; r++) c[mt][nt][r] = 0.0f;

            auto issue = [&](int s) {
                const uint32_t st = sb + (uint32_t)s * (STG_FL * 4);
                CPA16(st + dA, a_src);
                CPA16(st + dL, l_src);
                CPA16(st + dWa, w_src);
                CPA16(st + dWl, w_src + WOFF);
                asm volatile("cp.async.commit_group;");
                a_src += 16;  l_src += 16;
                w_src += 16 * Fn;
            };

            issue(0);

#pragma unroll 1
            for (int it = 0; it < 32; ++it) {
                const int s = it & 1;
                if (it < 31) {
                    issue(s ^ 1);
                    asm volatile("cp.async.wait_group 1;");
                } else {
                    asm volatile("cp.async.wait_group 0;");
                }
                __syncthreads();

                const float* at = smem + s * STG_FL;                      // AL 128x20
                const float* wt = smem + s * STG_FL + 2560 + role * 1152; // W 16x72

#pragma unroll
                for (int ks = 0; ks < 2; ks++) {
                    const int k0 = ks * 8 + tig;
                    uint32_t af[2][4], bf[4][2];
#pragma unroll
                    for (int mt = 0; mt < 2; mt++) {
                        const int arow = role * 64 + wm * 32 + mt * 16 + g;
                        af[mt][0] = __float_as_uint(at[arow * 20 + k0]);
                        af[mt][1] = __float_as_uint(at[(arow + 8) * 20 + k0]);
                        af[mt][2] = __float_as_uint(at[arow * 20 + k0 + 4]);
                        af[mt][3] = __float_as_uint(at[(arow + 8) * 20 + k0 + 4]);
                    }
#pragma unroll
                    for (int nt = 0; nt < 4; nt++) {
                        const int n0 = wn_ * 32 + nt * 8 + g;
                        bf[nt][0] = __float_as_uint(wt[k0 * 72 + n0]);
                        bf[nt][1] = __float_as_uint(wt[(k0 + 4) * 72 + n0]);
                    }
#pragma unroll
                    for (int mt = 0; mt < 2; mt++)
#pragma unroll
                        for (int nt = 0; nt < 4; nt++) {
                            asm volatile(
                                "mma.sync.aligned.m16n8k8.row.col.f32.tf32.tf32.f32 "
                                "{%0,%1,%2,%3}, {%4,%5,%6,%7}, {%8,%9}, {%0,%1,%2,%3};"
                                : "+f"(c[mt][nt][0]), "+f"(c[mt][nt][1]),
                                  "+f"(c[mt][nt][2]), "+f"(c[mt][nt][3])
                                : "r"(af[mt][0]), "r"(af[mt][1]),
                                  "r"(af[mt][2]), "r"(af[mt][3]),
                                  "r"(bf[nt][0]), "r"(bf[nt][1]));
                        }
                }
                __syncthreads();
            }

            // Epilogue: write projection tiles to global (L2-resident).
            float* gbase = (role == 0)
                ? (g_a + (size_t)(b * Tn + tb * 64) * Fn)
                : (g_l + (size_t)(b * Un) * Fn);
#pragma unroll
            for (int nt = 0; nt < 4; nt++) {
                const int col = wn_ * 32 + nt * 8 + 2 * tig;
                float b0 = 0.0f, b1 = 0.0f;
                if (role == 0) {
                    b0 = bias[fb * 64 + col];
                    b1 = bias[fb * 64 + col + 1];
                }
#pragma unroll
                for (int mt = 0; mt < 2; mt++) {
                    const int lr = wm * 32 + mt * 16 + g;
                    float2 v0 = { c[mt][nt][0] + b0, c[mt][nt][1] + b1 };
                    float2 v1 = { c[mt][nt][2] + b0, c[mt][nt][3] + b1 };
                    float* p = gbase + (size_t)lr * Fn + fb * 64 + col;
                    *(float2*)p            = v0;
                    *(float2*)(p + 8 * Fn) = v1;
                }
            }
            // Publish: fence all threads' stores, then one release increment.
            __threadfence();
            __syncthreads();
            if (tid == 0) atomicAdd(&g_cnt[b * 4 + tb], 1u);
        }
    } else {
        // ========================= bcast consumer =========================
        const int j   = bid - NGEMM;          // 0..2047, b-major
        const int b   = j >> 8;
        const int tb8 = (j >> 3) & 31;
        const int fb  = j & 7;

        // Wait until all 16 fb-tiles of (b, tb8/8) are published.
        if (tid == 0) {
            const unsigned* p = &g_cnt[b * 4 + (tb8 >> 3)];
            unsigned v;
            while (true) {
                asm volatile("ld.acquire.gpu.global.u32 %0, [%1];"
                             : "=r"(v) : "l"(p));
                if (v >= 16u) break;
                __nanosleep(256);
            }
        }
        __syncthreads();

        float* sa = smem;            // 8 x 128
        float* sl = smem + 1024;     // 64 x 128

        // Load a tile: 8 rows x 128 f.
        {
            int r = tid >> 5, c = tid & 31;
            const float4* src = (const float4*)(g_a
                + (size_t)(b * Tn + tb8 * 8 + r) * Fn + fb * 128);
            ((float4*)(sa + r * 128))[c] = src[c];
        }
        // Load l tile: 64 rows x 128 f.
#pragma unroll
        for (int i = 0; i < 8; i++) {
            int id = tid + i * 256;
            int r = id >> 5, c = id & 31;
            const float4* src = (const float4*)(g_l
                + (size_t)(b * Un + r) * Fn + fb * 128);
            ((float4*)(sl + r * 128))[c] = src[c];
        }
        __syncthreads();

        const int r = tid >> 5;
        const int c = tid & 31;
        float4* out4 = (float4*)out;
        const size_t base = (size_t)(b * Tn + tb8 * 8) * Un * (Fn / 4)
                            + (size_t)fb * 32 + c;

#pragma unroll 2
        for (int it = 0; it < 64; it++) {
            int rowLocal = it * 8 + r;          // 0..511
            int t = rowLocal >> 6;              // 0..7
            int u = rowLocal & 63;              // 0..63
            float4 va = ((const float4*)(sa + t * 128))[c];
            float4 vl = ((const float4*)(sl + u * 128))[c];
            float4 v;
            v.x = va.x + vl.x; v.y = va.y + vl.y;
            v.z = va.z + vl.z; v.w = va.w + vl.w;
            __stcs(&out4[base + (size_t)rowLocal * (Fn / 4)], v);
        }
    }
}

// ---------------------------------------------------------------------------
extern "C" void kernel_launch(void* const* d_in, const int* in_sizes, int n_in,
                              void* d_out, int out_size)
{
    const float* audio = (const float*)d_in[0];   // (8,256,512)
    const float* label = (const float*)d_in[1];   // (8,64,512)
    const float* W     = (const float*)d_in[2];   // (1024,1024)
    const float* bias  = (const float*)d_in[3];   // (1024,)
    float* out = (float*)d_out;                   // (8,256,64,1024)

    prep_kernel<<<2304, 256>>>(audio, label, W);
    joint_main<<<NGEMM + 2048, 256, SMEM_BYTES>>>(bias, out);
}

// round 14
// speedup vs baseline: 1.4110x; 1.4110x over previous
#include <cuda_runtime.h>
#include <cstdint>

// Problem constants
#define Bn 8
#define Tn 256
#define Un 64
#define Hn 512
#define Fn 1024

// Device scratch (no cudaMalloc allowed)
__device__ float g_act[(Bn * Tn + Bn * Un) * Hn];  // tf32-rounded inputs, 5 MB
__device__ float g_w[2 * Hn * Fn];                 // tf32-rounded W, 4 MB
__device__ float g_l[Bn * Un * Fn];                // label projection, 2 MB

__device__ __forceinline__ float to_tf32(float x) {
    float r;
    asm("cvt.rna.tf32.f32 %0, %1;" : "=f"(r) : "f"(x));
    return r;
}

// ---------------------------------------------------------------------------
// Prep: round GEMM operands to tf32 (RNA) once.
// ---------------------------------------------------------------------------
__global__ __launch_bounds__(256)
void prep_kernel(const float* __restrict__ audio,
                 const float* __restrict__ label,
                 const float* __restrict__ W)
{
    const int NA = Bn * Tn * Hn / 4;   // 262144 float4
    const int NL = Bn * Un * Hn / 4;   // 65536
    int i = blockIdx.x * 256 + threadIdx.x;
    const float4* src;
    float4* dst;
    if (i < NA)           { src = (const float4*)audio + i;         dst = (float4*)g_act + i; }
    else if (i < NA + NL) { src = (const float4*)label + (i - NA);  dst = (float4*)g_act + i; }
    else                  { src = (const float4*)W + (i - NA - NL); dst = (float4*)g_w + (i - NA - NL); }
    float4 v = *src;
    float4 o = { to_tf32(v.x), to_tf32(v.y), to_tf32(v.z), to_tf32(v.w) };
    *dst = o;
}

// ---------------------------------------------------------------------------
// Label GEMM: g_l = label @ Wl. M=512 (8b x 64u), N=1024, K=512.
// BM=128, BN=64, BK=32, 256 threads, warp grid 4(M)x2(N), warp tile 32x32.
// Double-buffered (round-4 verified code, label-only). 64 CTAs, ~3 us.
// ---------------------------------------------------------------------------
__global__ __launch_bounds__(256, 3)
void label_gemm(void)
{
    const int bc = blockIdx.x;          // 0..15  (N tile of 64)
    const int br = blockIdx.y;          // 0..3   (M tile of 128)

    const float* Abase = g_act + (size_t)(Bn * Tn + br * 128) * Hn;
    const float* Wbase = g_w + (size_t)Hn * Fn + bc * 64;
    float* Cbase = g_l + (size_t)br * 128 * Fn + bc * 64;

    __shared__ float As[2][128][36];
    __shared__ float Bs[2][32][72];

    const int tid = threadIdx.x;
    const int warp = tid >> 5;
    const int lane = tid & 31;
    const int warpM = warp >> 1;        // 0..3
    const int warpN = warp & 1;         // 0..1
    const int g = lane >> 2;
    const int tig = lane & 3;

    float c[2][4][4];
#pragma unroll
    for (int mt = 0; mt < 2; mt++)
#pragma unroll
        for (int nt = 0; nt < 4; nt++)
#pragma unroll
            for (int r = 0; r < 4; r++) c[mt][nt][r] = 0.0f;

    const int ar[4] = { (tid + 0) >> 3, (tid + 256) >> 3, (tid + 512) >> 3, (tid + 768) >> 3 };
    const int ac = tid & 7;
    const int bk[2] = { (tid + 0) >> 4, (tid + 256) >> 4 };
    const int bn = tid & 15;

    float4 ra[4], rb[2];
#pragma unroll
    for (int i = 0; i < 4; i++)
        ra[i] = *(const float4*)(Abase + (size_t)ar[i] * Hn + ac * 4);
#pragma unroll
    for (int i = 0; i < 2; i++)
        rb[i] = *(const float4*)(Wbase + (size_t)bk[i] * Fn + bn * 4);

    const int NITER = Hn / 32;  // 16
    for (int it = 0; it < NITER; it++) {
        const int buf = it & 1;
#pragma unroll
        for (int i = 0; i < 4; i++)
            *(float4*)(&As[buf][ar[i]][ac * 4]) = ra[i];
#pragma unroll
        for (int i = 0; i < 2; i++)
            *(float4*)(&Bs[buf][bk[i]][bn * 4]) = rb[i];
        __syncthreads();

        if (it + 1 < NITER) {
            const int kt = (it + 1) * 32;
#pragma unroll
            for (int i = 0; i < 4; i++)
                ra[i] = *(const float4*)(Abase + (size_t)ar[i] * Hn + kt + ac * 4);
#pragma unroll
            for (int i = 0; i < 2; i++)
                rb[i] = *(const float4*)(Wbase + (size_t)(kt + bk[i]) * Fn + bn * 4);
        }

#pragma unroll
        for (int ks = 0; ks < 4; ks++) {
            uint32_t af[2][4], bf[4][2];
            const int k0 = ks * 8 + tig;
#pragma unroll
            for (int mt = 0; mt < 2; mt++) {
                int r0 = warpM * 32 + mt * 16 + g;
                af[mt][0] = __float_as_uint(As[buf][r0][k0]);
                af[mt][1] = __float_as_uint(As[buf][r0 + 8][k0]);
                af[mt][2] = __float_as_uint(As[buf][r0][k0 + 4]);
                af[mt][3] = __float_as_uint(As[buf][r0 + 8][k0 + 4]);
            }
#pragma unroll
            for (int nt = 0; nt < 4; nt++) {
                int n0 = warpN * 32 + nt * 8 + g;
                bf[nt][0] = __float_as_uint(Bs[buf][k0][n0]);
                bf[nt][1] = __float_as_uint(Bs[buf][k0 + 4][n0]);
            }
#pragma unroll
            for (int mt = 0; mt < 2; mt++)
#pragma unroll
                for (int nt = 0; nt < 4; nt++) {
                    asm volatile(
                        "mma.sync.aligned.m16n8k8.row.col.f32.tf32.tf32.f32 "
                        "{%0,%1,%2,%3}, {%4,%5,%6,%7}, {%8,%9}, {%0,%1,%2,%3};"
                        : "+f"(c[mt][nt][0]), "+f"(c[mt][nt][1]),
                          "+f"(c[mt][nt][2]), "+f"(c[mt][nt][3])
                        : "r"(af[mt][0]), "r"(af[mt][1]),
                          "r"(af[mt][2]), "r"(af[mt][3]),
                          "r"(bf[nt][0]), "r"(bf[nt][1]));
                }
        }
        __syncthreads();
    }

#pragma unroll
    for (int nt = 0; nt < 4; nt++) {
        int col = warpN * 32 + nt * 8 + 2 * tig;
#pragma unroll
        for (int mt = 0; mt < 2; mt++) {
            int row = warpM * 32 + mt * 16 + g;
            float2 v0 = { c[mt][nt][0], c[mt][nt][1] };
            float2 v1 = { c[mt][nt][2], c[mt][nt][3] };
            *(float2*)(Cbase + (size_t)row * Fn + col) = v0;
            *(float2*)(Cbase + (size_t)(row + 8) * Fn + col) = v1;
        }
    }
}

// ---------------------------------------------------------------------------
// Fused kernel (round-6 structure, audio-only GEMM).
// CTA = (b, 64 t, 32 f). Grid 1024, 4/SM (the measured-best wave regime).
// GEMM: M=64 audio rows, N=32, K=512, BK=32 (16 iters), 8 warps
//   (warp grid 4(M)x2(N), warp tile 16x16), tf32 m16n8k8, 2-stage cp.async.
// The label tile (64x32) is cp.async'd from g_l in its own group before the
//   pipeline; it lands during the mainloop.
// Epilogue: Ca (+bias) staged to smem (64x32, pitch 40); store phase streams
//   out[t,u,f] = Ca[t,f] + L[u,f] with .cs float4 stores (round-6 proven).
// SMEM floats: stage0 A 64x36 @0, W 32x40 @2304; stage = 3584; stage1 @3584;
//   L tile 64x40 @7168. Total = 9728 fl = 38912 B. Ca unions into stage0.
// ---------------------------------------------------------------------------
#define STG_FL 3584
#define L_OFF  7168
#define SMEM_BYTES 38912

extern __shared__ float smem[];

#define CPA16(dst, src) \
    asm volatile("cp.async.cg.shared.global [%0], [%1], 16;" :: "r"(dst), "l"(src))

__global__ __launch_bounds__(256, 4)
void joint_fused(const float* __restrict__ bias, float* __restrict__ out)
{
    const int fb = blockIdx.x;            // 0..31  (f tile of 32)
    const int tb = blockIdx.y;            // 0..3   (t tile of 64)
    const int b  = blockIdx.z;            // 0..7

    const int tid  = threadIdx.x;
    const int warp = tid >> 5;
    const int lane = tid & 31;
    const int wm   = warp >> 1;           // 0..3 (M)
    const int wn_  = warp & 1;            // 0..1 (N)
    const int g    = lane >> 2;           // 0..7
    const int tig  = lane & 3;            // 0..3

    const uint32_t sb = (uint32_t)__cvta_generic_to_shared(smem);

    // ---- L-tile cp.async (own group, lands during mainloop) ----
    {
        const int rl = tid >> 2;          // 0..63
        const int cl = tid & 3;           // unused high bits
        // 64 rows x 8 float4 = 512 float4 -> 2 per thread
#pragma unroll
        for (int i = 0; i < 2; i++) {
            int id = tid + i * 256;
            int r = id >> 3, cc = id & 7;
            const float* src = g_l + (size_t)(b * Un + r) * Fn + fb * 32 + cc * 4;
            CPA16(sb + (uint32_t)(L_OFF + r * 40 + cc * 4) * 4, src);
        }
        asm volatile("cp.async.commit_group;");
        (void)rl; (void)cl;
    }

    // ---- GEMM cp.async coordinates ----
    // A: 64 rows x 8 float4 = 512 float4 -> 2/thread.
    int rA[2], cA[2];
    uint32_t dA[2];
#pragma unroll
    for (int i = 0; i < 2; i++) {
        int id = tid + i * 256;
        rA[i] = id >> 3;  cA[i] = id & 7;
        dA[i] = (uint32_t)(rA[i] * 36 + cA[i] * 4) * 4;
    }
    const float* a_src[2];
#pragma unroll
    for (int i = 0; i < 2; i++)
        a_src[i] = g_act + (size_t)(b * Tn + tb * 64 + rA[i]) * Hn + cA[i] * 4;
    // W: 32 rows x 8 float4 = 256 -> 1/thread.
    const int kr = tid >> 3;
    const int cw = tid & 7;
    const float* w_src = g_w + (size_t)kr * Fn + fb * 32 + cw * 4;
    const uint32_t dW = (uint32_t)(2304 + kr * 40 + cw * 4) * 4;

    float c[2][4];
#pragma unroll
    for (int nt = 0; nt < 2; nt++)
#pragma unroll
        for (int r = 0; r < 4; r++) c[nt][r] = 0.0f;

    auto issue = [&](int s) {
        const uint32_t st = sb + (uint32_t)s * (STG_FL * 4);
#pragma unroll
        for (int i = 0; i < 2; i++) CPA16(st + dA[i], a_src[i]);
        CPA16(st + dW, w_src);
        asm volatile("cp.async.commit_group;");
#pragma unroll
        for (int i = 0; i < 2; i++) a_src[i] += 32;
        w_src += 32 * Fn;
    };

    issue(0);

#pragma unroll 1
    for (int it = 0; it < 16; ++it) {
        const int s = it & 1;
        if (it < 15) {
            issue(s ^ 1);
            asm volatile("cp.async.wait_group 1;");
        } else {
            asm volatile("cp.async.wait_group 0;");   // also drains L tile
        }
        __syncthreads();

        const float* at = smem + s * STG_FL;          // A 64x36
        const float* wt = smem + s * STG_FL + 2304;   // W 32x40

#pragma unroll
        for (int ks = 0; ks < 4; ks++) {
            const int k0 = ks * 8 + tig;
            uint32_t af[4], bf[2][2];
            const int arow = wm * 16 + g;
            af[0] = __float_as_uint(at[arow * 36 + k0]);
            af[1] = __float_as_uint(at[(arow + 8) * 36 + k0]);
            af[2] = __float_as_uint(at[arow * 36 + k0 + 4]);
            af[3] = __float_as_uint(at[(arow + 8) * 36 + k0 + 4]);
#pragma unroll
            for (int nt = 0; nt < 2; nt++) {
                const int n0 = wn_ * 16 + nt * 8 + g;
                bf[nt][0] = __float_as_uint(wt[k0 * 40 + n0]);
                bf[nt][1] = __float_as_uint(wt[(k0 + 4) * 40 + n0]);
            }
#pragma unroll
            for (int nt = 0; nt < 2; nt++) {
                asm volatile(
                    "mma.sync.aligned.m16n8k8.row.col.f32.tf32.tf32.f32 "
                    "{%0,%1,%2,%3}, {%4,%5,%6,%7}, {%8,%9}, {%0,%1,%2,%3};"
                    : "+f"(c[nt][0]), "+f"(c[nt][1]),
                      "+f"(c[nt][2]), "+f"(c[nt][3])
                    : "r"(af[0]), "r"(af[1]), "r"(af[2]), "r"(af[3]),
                      "r"(bf[nt][0]), "r"(bf[nt][1]));
            }
        }
        __syncthreads();
    }

    // ---- Stage Ca into SMEM: 64 rows x 32 f, pitch 40 (unions stage 0) ----
    float* Cs = smem;
#pragma unroll
    for (int nt = 0; nt < 2; nt++) {
        const int col = wn_ * 16 + nt * 8 + 2 * tig;
        const float b0 = bias[fb * 32 + col];
        const float b1 = bias[fb * 32 + col + 1];
        const int row = wm * 16 + g;
        float2 v0 = { c[nt][0] + b0, c[nt][1] + b1 };
        float2 v1 = { c[nt][2] + b0, c[nt][3] + b1 };
        *(float2*)&Cs[row * 40 + col]       = v0;
        *(float2*)&Cs[(row + 8) * 40 + col] = v1;
    }
    __syncthreads();

    // ---- Broadcast store (round-6 proven layout) ----
    const float4* Ca4 = (const float4*)smem;              // pitch 10
    const float4* L4  = (const float4*)(smem + L_OFF);    // pitch 10
    float4* out4 = (float4*)out;
    const int fi = lane & 7;
    const int uh = lane >> 3;

    float4 lreg[2];
#pragma unroll
    for (int i = 0; i < 2; i++) {
        const int u = warp * 8 + i * 4 + uh;
        lreg[i] = L4[u * 10 + fi];
    }

    const size_t row0 = ((size_t)(b * Tn + tb * 64) * Un) * (Fn / 4) + fb * 8 + fi;

#pragma unroll 2
    for (int tt = 0; tt < 64; ++tt) {
        const float4 a = Ca4[tt * 10 + fi];
        const size_t tbase = row0 + (size_t)tt * Un * (Fn / 4);
#pragma unroll
        for (int i = 0; i < 2; i++) {
            const int u = warp * 8 + i * 4 + uh;
            float4 v = { a.x + lreg[i].x, a.y + lreg[i].y,
                         a.z + lreg[i].z, a.w + lreg[i].w };
            __stcs(out4 + tbase + (size_t)u * (Fn / 4), v);
        }
    }
}

// ---------------------------------------------------------------------------
extern "C" void kernel_launch(void* const* d_in, const int* in_sizes, int n_in,
                              void* d_out, int out_size)
{
    const float* audio = (const float*)d_in[0];   // (8,256,512)
    const float* label = (const float*)d_in[1];   // (8,64,512)
    const float* W     = (const float*)d_in[2];   // (1024,1024)
    const float* bias  = (const float*)d_in[3];   // (1024,)
    float* out = (float*)d_out;                   // (8,256,64,1024)

    cudaFuncSetAttribute(joint_fused,
                         cudaFuncAttributeMaxDynamicSharedMemorySize, SMEM_BYTES);

    prep_kernel<<<2304, 256>>>(audio, label, W);
    label_gemm<<<dim3(16, 4), 256>>>();
    joint_fused<<<dim3(32, 4, 8), 256, SMEM_BYTES>>>(bias, out);
}

// round 16
// speedup vs baseline: 1.7862x; 1.2659x over previous
#include <cuda_runtime.h>
#include <cstdint>

// Problem constants
#define Bn 8
#define Tn 256
#define Un 64
#define Hn 512
#define Fn 1024

// tf32-prerounded copies (no cudaMalloc -> device globals).
// g_act: audio rows [0, 2048), label rows [2048, 2560).
__device__ float g_act[(Bn * Tn + Bn * Un) * Hn];  // 5 MB
__device__ float g_w[2 * Hn * Fn];                 // 4 MB

__device__ __forceinline__ float to_tf32(float x) {
    float r;
    asm("cvt.rna.tf32.f32 %0, %1;" : "=f"(r) : "f"(x));
    return r;
}

// ---------------------------------------------------------------------------
// Prep: round all GEMM operands to tf32 (RNA) once.
// ---------------------------------------------------------------------------
__global__ __launch_bounds__(256)
void prep_kernel(const float* __restrict__ audio,
                 const float* __restrict__ label,
                 const float* __restrict__ W)
{
    const int NA = Bn * Tn * Hn / 4;   // 262144 float4
    const int NL = Bn * Un * Hn / 4;   // 65536
    int i = blockIdx.x * 256 + threadIdx.x;
    const float4* src;
    float4* dst;
    if (i < NA)           { src = (const float4*)audio + i;         dst = (float4*)g_act + i; }
    else if (i < NA + NL) { src = (const float4*)label + (i - NA);  dst = (float4*)g_act + i; }
    else                  { src = (const float4*)W + (i - NA - NL); dst = (float4*)g_w + (i - NA - NL); }
    float4 v = *src;
    float4 o = { to_tf32(v.x), to_tf32(v.y), to_tf32(v.z), to_tf32(v.w) };
    *dst = o;
}

// ---------------------------------------------------------------------------
// Warp-specialized persistent fused kernel, double-buffered C handoff.
// 256 CTAs (2/SM), 512 threads: warps 0-7 GEMM (0-3 audio, 4-7 label),
// warps 8-15 store. 1024 tiles of (b, 64 t, 32 f); CTA does EXACTLY 4 tiles
// (idx = bid + 256k) -> zero tail imbalance.
// Per tile GEMM: M=128 (64 audio t + 64 label u), N=32, K=512, BK=32,
//   warp tile 32x16, tf32 m16n8k8, 2-stage cp.async (16 iters, bar 1).
// Handoff (p = k&1, two C buffers):
//   producer: [k>=2: bar.sync(4+p,512)]  -> STS C_p -> membar.cta
//             -> bar.arrive(2+p,512)   (NON-blocking publish)
//   consumer: bar.sync(2+p,512) -> LDS+STG -> [k<=1: bar.arrive(4+p,512)]
//   Consumer LDS completion is guaranteed before its arrive because every
//   LDS result feeds an issued STG (register dependency). Producer STS are
//   drained by membar.cta before the publish arrive.
//   => store(tile k) fully overlaps GEMM(tile k+1); no deadlock, counts match.
// SMEM: stages 2 x 7168 fl (57344 B) + C 2 x 5120 fl (40960 B) = 98304 B.
// ---------------------------------------------------------------------------
#define STG_FL 7168
#define C_OFF  14336            // float offset of C buffers
#define C_FL   5120
#define SMEM_BYTES 98304
#define NCTAS  256
#define KTILES 4

extern __shared__ float smem[];

#define CPA16(dst, src) \
    asm volatile("cp.async.cg.shared.global [%0], [%1], 16;" :: "r"(dst), "l"(src))
#define BAR_SYNC(id, cnt) \
    asm volatile("bar.sync %0, %1;" :: "r"(id), "r"(cnt) : "memory")
#define BAR_ARRIVE(id, cnt) \
    asm volatile("bar.arrive %0, %1;" :: "r"(id), "r"(cnt) : "memory")

__global__ __launch_bounds__(512, 2)
void joint_fused(const float* __restrict__ bias, float* __restrict__ out)
{
    const int tid  = threadIdx.x;
    const int warp = tid >> 5;
    const int lane = tid & 31;
    const uint32_t sb = (uint32_t)__cvta_generic_to_shared(smem);

    if (warp < 8) {
        // ===================== GEMM producer (256 threads) ==================
        const int role = warp >> 2;           // 0 = audio, 1 = label
        const int w4   = warp & 3;
        const int wm   = w4 >> 1;
        const int wn_  = w4 & 1;
        const int g    = lane >> 2;
        const int tig  = lane & 3;

        // cp.async fixed per-thread coordinates
        int rA[2], cA[2];
        uint32_t dA[2];
#pragma unroll
        for (int i = 0; i < 2; i++) {
            int id = tid + i * 256;
            rA[i] = id >> 3;  cA[i] = id & 7;
            dA[i] = (uint32_t)(rA[i] * 36 + cA[i] * 4) * 4;
        }
        const int kr = tid >> 3;
        const int cw = tid & 7;
        const uint32_t dWa = (uint32_t)(4608 + kr * 40 + cw * 4) * 4;
        const uint32_t dWl = dWa + 1280u * 4;
        const int WOFF = Hn * Fn;

#pragma unroll 1
        for (int k = 0; k < KTILES; ++k) {
            const int idx = blockIdx.x + NCTAS * k;
            const int fb = idx & 31;
            const int tb = (idx >> 5) & 3;
            const int b  = idx >> 7;
            const int p  = k & 1;

            const float* a0 = g_act + (size_t)(b * Tn + tb * 64) * Hn;
            const float* l0 = g_act + (size_t)(Bn * Tn + b * Un) * Hn;

            float c[2][2][4];
#pragma unroll
            for (int mt = 0; mt < 2; mt++)
#pragma unroll
                for (int nt = 0; nt < 2; nt++)
#pragma unroll
                    for (int r = 0; r < 4; r++) c[mt][nt][r] = 0.0f;

            const float* a_src[2];
            const float* l_src[2];
#pragma unroll
            for (int i = 0; i < 2; i++) {
                a_src[i] = a0 + (size_t)rA[i] * Hn + cA[i] * 4;
                l_src[i] = l0 + (size_t)rA[i] * Hn + cA[i] * 4;
            }
            const float* wa_src = g_w + (size_t)kr * Fn + fb * 32 + cw * 4;
            const float* wl_src = wa_src + WOFF;

            auto issue = [&](int s) {
                const uint32_t st = sb + (uint32_t)s * (STG_FL * 4);
#pragma unroll
                for (int i = 0; i < 2; i++) {
                    CPA16(st + dA[i], a_src[i]);
                    CPA16(st + dA[i] + 9216u, l_src[i]);
                }
                CPA16(st + dWa, wa_src);
                CPA16(st + dWl, wl_src);
                asm volatile("cp.async.commit_group;");
#pragma unroll
                for (int i = 0; i < 2; i++) { a_src[i] += 32; l_src[i] += 32; }
                wa_src += 32 * Fn;  wl_src += 32 * Fn;
            };

            issue(0);

#pragma unroll 1
            for (int it = 0; it < 16; ++it) {
                const int s = it & 1;
                if (it < 15) {
                    issue(s ^ 1);
                    asm volatile("cp.async.wait_group 1;");
                } else {
                    asm volatile("cp.async.wait_group 0;");
                }
                BAR_SYNC(1, 256);

                const float* at = smem + s * STG_FL;
                const float* wt = smem + s * STG_FL + 4608 + role * 1280;

#pragma unroll
                for (int ks = 0; ks < 4; ks++) {
                    const int k0 = ks * 8 + tig;
                    uint32_t af[2][4], bf[2][2];
#pragma unroll
                    for (int mt = 0; mt < 2; mt++) {
                        const int arow = role * 64 + wm * 32 + mt * 16 + g;
                        af[mt][0] = __float_as_uint(at[arow * 36 + k0]);
                        af[mt][1] = __float_as_uint(at[(arow + 8) * 36 + k0]);
                        af[mt][2] = __float_as_uint(at[arow * 36 + k0 + 4]);
                        af[mt][3] = __float_as_uint(at[(arow + 8) * 36 + k0 + 4]);
                    }
#pragma unroll
                    for (int nt = 0; nt < 2; nt++) {
                        const int n0 = wn_ * 16 + nt * 8 + g;
                        bf[nt][0] = __float_as_uint(wt[k0 * 40 + n0]);
                        bf[nt][1] = __float_as_uint(wt[(k0 + 4) * 40 + n0]);
                    }
#pragma unroll
                    for (int mt = 0; mt < 2; mt++)
#pragma unroll
                        for (int nt = 0; nt < 2; nt++) {
                            asm volatile(
                                "mma.sync.aligned.m16n8k8.row.col.f32.tf32.tf32.f32 "
                                "{%0,%1,%2,%3}, {%4,%5,%6,%7}, {%8,%9}, {%0,%1,%2,%3};"
                                : "+f"(c[mt][nt][0]), "+f"(c[mt][nt][1]),
                                  "+f"(c[mt][nt][2]), "+f"(c[mt][nt][3])
                                : "r"(af[mt][0]), "r"(af[mt][1]),
                                  "r"(af[mt][2]), "r"(af[mt][3]),
                                  "r"(bf[nt][0]), "r"(bf[nt][1]));
                        }
                }
                BAR_SYNC(1, 256);
            }

            // Wait for buffer p to be free (consumer's arrive from tile k-2).
            if (k >= 2) BAR_SYNC(4 + p, 512);

            float* Cs = smem + C_OFF + p * C_FL;    // 128 x 32, pitch 40
#pragma unroll
            for (int nt = 0; nt < 2; nt++) {
                const int col = wn_ * 16 + nt * 8 + 2 * tig;
                float b0 = 0.0f, b1 = 0.0f;
                if (role == 0) {
                    b0 = bias[fb * 32 + col];
                    b1 = bias[fb * 32 + col + 1];
                }
#pragma unroll
                for (int mt = 0; mt < 2; mt++) {
                    const int row = role * 64 + wm * 32 + mt * 16 + g;
                    float2 v0 = { c[mt][nt][0] + b0, c[mt][nt][1] + b1 };
                    float2 v1 = { c[mt][nt][2] + b0, c[mt][nt][3] + b1 };
                    *(float2*)&Cs[row * 40 + col]       = v0;
                    *(float2*)&Cs[(row + 8) * 40 + col] = v1;
                }
            }
            // Drain STS, then non-blocking publish.
            asm volatile("membar.cta;" ::: "memory");
            BAR_ARRIVE(2 + p, 512);
        }
    } else {
        // ===================== Store consumer (256 threads) =================
        const int sw = warp - 8;          // 0..7
        const int fi = lane & 7;          // float4 within 32-f row
        const int uh = lane >> 3;         // 0..3

        float4* out4 = (float4*)out;
#pragma unroll 1
        for (int k = 0; k < KTILES; ++k) {
            const int idx = blockIdx.x + NCTAS * k;
            const int fb = idx & 31;
            const int tb = (idx >> 5) & 3;
            const int b  = idx >> 7;
            const int p  = k & 1;

            BAR_SYNC(2 + p, 512);          // wait for published C_p
            const float4* C4 = (const float4*)(smem + C_OFF + p * C_FL); // pitch 10

            float4 lreg[2];
#pragma unroll
            for (int i = 0; i < 2; i++) {
                const int u = sw * 8 + i * 4 + uh;
                lreg[i] = C4[(64 + u) * 10 + fi];
            }

            const size_t row0 = ((size_t)(b * Tn + tb * 64) * Un) * (Fn / 4)
                                + fb * 8 + fi;
#pragma unroll 2
            for (int tt = 0; tt < 64; ++tt) {
                const float4 a = C4[tt * 10 + fi];
                const size_t tbase = row0 + (size_t)tt * Un * (Fn / 4);
#pragma unroll
                for (int i = 0; i < 2; i++) {
                    const int u = sw * 8 + i * 4 + uh;
                    float4 v = { a.x + lreg[i].x, a.y + lreg[i].y,
                                 a.z + lreg[i].z, a.w + lreg[i].w };
                    __stcs(out4 + tbase + (size_t)u * (Fn / 4), v);
                }
            }
            // Release buffer p for tile k+2 (only needed for k <= KTILES-3).
            if (k <= KTILES - 3) BAR_ARRIVE(4 + p, 512);
        }
    }
}

// ---------------------------------------------------------------------------
extern "C" void kernel_launch(void* const* d_in, const int* in_sizes, int n_in,
                              void* d_out, int out_size)
{
    const float* audio = (const float*)d_in[0];   // (8,256,512)
    const float* label = (const float*)d_in[1];   // (8,64,512)
    const float* W     = (const float*)d_in[2];   // (1024,1024)
    const float* bias  = (const float*)d_in[3];   // (1024,)
    float* out = (float*)d_out;                   // (8,256,64,1024)

    cudaFuncSetAttribute(joint_fused,
                         cudaFuncAttributeMaxDynamicSharedMemorySize, SMEM_BYTES);

    prep_kernel<<<2304, 256>>>(audio, label, W);
    joint_fused<<<NCTAS, 512, SMEM_BYTES>>>(bias, out);
}